// round 12
// baseline (speedup 1.0000x reference)
#include <cuda_runtime.h>
#include <cuda_fp16.h>
#include <math.h>
#include <stdint.h>

typedef unsigned long long ull;

#define Bb 8
#define NN 1024
#define CC 544
#define JJ 17
#define FF 32
#define HH 8
#define HD 68
#define QC 1632
#define DP 80     // padded head dim

// tensor-core warp ops (family-common PTX, OK on plain sm_103 target)
#define LDSM4(r0,r1,r2,r3,addr) \
    asm volatile("ldmatrix.sync.aligned.m8n8.x4.shared.b16 {%0,%1,%2,%3}, [%4];" \
        : "=r"(r0),"=r"(r1),"=r"(r2),"=r"(r3) : "r"(addr))
#define LDSM4T(r0,r1,r2,r3,addr) \
    asm volatile("ldmatrix.sync.aligned.m8n8.x4.trans.shared.b16 {%0,%1,%2,%3}, [%4];" \
        : "=r"(r0),"=r"(r1),"=r"(r2),"=r"(r3) : "r"(addr))
#define MMAH(d,a,b) \
    asm volatile("mma.sync.aligned.m16n8k16.row.col.f32.f16.f16.f32 " \
        "{%0,%1,%2,%3}, {%4,%5,%6,%7}, {%8,%9}, {%0,%1,%2,%3};" \
        : "+f"((d)[0]),"+f"((d)[1]),"+f"((d)[2]),"+f"((d)[3]) \
        : "r"((a)[0]),"r"((a)[1]),"r"((a)[2]),"r"((a)[3]), "r"((b)[0]),"r"((b)[1]))

#define CP16(dst, src) \
    asm volatile("cp.async.cg.shared.global [%0], [%1], 16;" \
        :: "r"(dst), "l"(src) : "memory")
#define CP16Z(dst, src, sz) \
    asm volatile("cp.async.cg.shared.global [%0], [%1], 16, %2;" \
        :: "r"(dst), "l"(src), "r"(sz) : "memory")
#define CPCOMMIT() asm volatile("cp.async.commit_group;" ::: "memory")
#define CPWAIT1()  asm volatile("cp.async.wait_group 1;" ::: "memory")
#define CPWAIT0()  asm volatile("cp.async.wait_group 0;" ::: "memory")

__device__ __forceinline__ uint32_t smem_u32(const void* p) {
    uint32_t a;
    asm("{ .reg .u64 t; cvta.to.shared.u64 t, %1; cvt.u32.u64 %0, t; }" : "=r"(a) : "l"(p));
    return a;
}
__device__ __forceinline__ const void* gptr(const void* p) {
    return (const void*)__cvta_generic_to_global(p);
}
__device__ __forceinline__ uint32_t packh2(float v0, float v1) {
    __half2 h = __floats2half2_rn(v0, v1);
    return *(uint32_t*)&h;
}

// -------- scratch --------
__device__ float g_sc [(size_t)Bb * NN * JJ];
__device__ float g_w  [(size_t)Bb * NN * JJ];
__device__ __half g_ah [(size_t)Bb * NN * CC];   // GEMM A (xp, then attn-out), fp16
__device__ __half g_qb [(size_t)QC * CC];        // qkv weights fp16
__device__ __half g_pb [(size_t)CC * CC];        // proj weights fp16
__device__ __half g_qh [(size_t)Bb * HH * NN * DP];
__device__ __half g_kh [(size_t)Bb * HH * NN * DP];   // pre-scaled by scl*pos_scale
__device__ __half g_vh [(size_t)Bb * HH * NN * DP];

__device__ __forceinline__ float wsum(float v) {
#pragma unroll
    for (int o = 16; o > 0; o >>= 1) v += __shfl_xor_sync(0xffffffffu, v, o);
    return v;
}
__device__ __forceinline__ float wmax(float v) {
#pragma unroll
    for (int o = 16; o > 0; o >>= 1) v = fmaxf(v, __shfl_xor_sync(0xffffffffu, v, o));
    return v;
}

// ---------------------------------------------------------------------------
// Kernel 1 (fused preprocessing): scores + weight fp16 converts + pad zeroing
// ---------------------------------------------------------------------------
#define PRE_SCORE 8192
#define PRE_CVTQ  (PRE_SCORE + 408)
#define PRE_CVTP  (PRE_CVTQ + 136)
#define PRE_PAD   (PRE_CVTP + 1446)

__global__ void k_pre(const float* __restrict__ x,
                      const float* __restrict__ ng,
                      const float* __restrict__ nb,
                      const float* __restrict__ apw,
                      const float* __restrict__ apb,
                      const float* __restrict__ qkv_w,
                      const float* __restrict__ proj_w) {
    int blk = blockIdx.x;
    int tid = threadIdx.x;
    if (blk < PRE_SCORE) {
        int bn = blk;
        int j = tid >> 5, f = tid & 31;
        float v = x[(size_t)bn * CC + j * FF + f];
        float mu = wsum(v) * (1.0f / FF);
        float d = v - mu;
        float var = wsum(d * d) * (1.0f / FF);
        float xn = d * rsqrtf(var + 1e-5f) * ng[f] + nb[f];
        float sc = wsum(xn * apw[f]);
        if (f == 0) g_sc[(size_t)bn * JJ + j] = sc + apb[0];
    } else if (blk < PRE_CVTQ) {
        int idx = (blk - PRE_SCORE) * 544 + tid;    // < 221952 exactly
        float4 v = ((const float4*)qkv_w)[idx];
        ((uint2*)g_qb)[idx] = make_uint2(packh2(v.x, v.y), packh2(v.z, v.w));
    } else if (blk < PRE_CVTP) {
        int idx = (blk - PRE_CVTQ) * 544 + tid;     // < 73984 exactly
        float4 v = ((const float4*)proj_w)[idx];
        ((uint2*)g_pb)[idx] = make_uint2(packh2(v.x, v.y), packh2(v.z, v.w));
    } else {
        int idx = (blk - PRE_CVTP) * 544 + tid;
        if (idx < 64 * 1024 * (DP - HD)) {
            int bhn = idx / (DP - HD), d = HD + (idx - bhn * (DP - HD));
            size_t ad = (size_t)bhn * DP + d;
            __half z = __float2half(0.f);
            g_qh[ad] = z; g_kh[ad] = z;
        }
    }
}

// ---------------------------------------------------------------------------
// Kernel 2: softmax over sequence axis N per (b, joint)
// ---------------------------------------------------------------------------
__global__ void k_softmax_seq() {
    int bj = blockIdx.x;
    int b = bj / JJ, j = bj - b * JJ;
    int tid = threadIdx.x;
    const float* base = g_sc + (size_t)b * NN * JJ + j;

    float v[4];
#pragma unroll
    for (int i = 0; i < 4; i++) v[i] = base[(size_t)(tid + i * 256) * JJ];

    __shared__ float red[8];
    __shared__ float bc;
    int wid = tid >> 5, lane = tid & 31;

    float mx = fmaxf(fmaxf(v[0], v[1]), fmaxf(v[2], v[3]));
    mx = wmax(mx);
    if (lane == 0) red[wid] = mx;
    __syncthreads();
    if (tid == 0) {
        float m = red[0];
        for (int i = 1; i < 8; i++) m = fmaxf(m, red[i]);
        bc = m;
    }
    __syncthreads();
    mx = bc;
    __syncthreads();

    float se = 0.f;
#pragma unroll
    for (int i = 0; i < 4; i++) { v[i] = __expf(v[i] - mx); se += v[i]; }
    se = wsum(se);
    if (lane == 0) red[wid] = se;
    __syncthreads();
    if (tid == 0) {
        float s = 0.f;
        for (int i = 0; i < 8; i++) s += red[i];
        bc = 1.0f / s;
    }
    __syncthreads();
    float inv = bc;

    float* wbase = g_w + (size_t)b * NN * JJ + j;
#pragma unroll
    for (int i = 0; i < 4; i++) wbase[(size_t)(tid + i * 256) * JJ] = v[i] * inv;
}

// ---------------------------------------------------------------------------
// Kernel 3: recompute joint-LN from x, pool, LN over C -> fp16
// ---------------------------------------------------------------------------
__global__ void k_pool_ln(const float* __restrict__ x,
                          const float* __restrict__ ng,
                          const float* __restrict__ nb,
                          const float* __restrict__ g2,
                          const float* __restrict__ b2) {
    int bn = blockIdx.x;
    int c = threadIdx.x;
    int wid = c >> 5, lane = c & 31;
    __shared__ float red[17];
    __shared__ float bc0, bc1;

    float xv = x[(size_t)bn * CC + c];
    float mu_j = wsum(xv) * (1.0f / FF);
    float dj = xv - mu_j;
    float var_j = wsum(dj * dj) * (1.0f / FF);
    float xn = dj * rsqrtf(var_j + 1e-5f) * ng[lane] + nb[lane];

    float v = xn * g_w[(size_t)bn * JJ + wid];

    float s = wsum(v);
    if (lane == 0) red[wid] = s;
    __syncthreads();
    if (wid == 0) {
        float t = (lane < 17) ? red[lane] : 0.f;
        t = wsum(t);
        if (lane == 0) bc0 = t * (1.0f / CC);
    }
    __syncthreads();
    float mu = bc0;
    float d = v - mu;

    float s2 = wsum(d * d);
    if (lane == 0) red[wid] = s2;
    __syncthreads();
    if (wid == 0) {
        float t = (lane < 17) ? red[lane] : 0.f;
        t = wsum(t);
        if (lane == 0) bc1 = t * (1.0f / CC);
    }
    __syncthreads();
    float var = bc1;

    float xp = d * rsqrtf(var + 1e-5f) * g2[c] + b2[c];
    g_ah[(size_t)bn * CC + c] = __float2half_rn(xp);
}

// ---------------------------------------------------------------------------
// cp.async double-buffered mma.sync fp16 GEMM.
// mode 0: fp32 C (+bias). mode 1: scatter QKV (K pre-scaled by scl*pos_scale).
// ---------------------------------------------------------------------------
#define GBM 128
#define GBN 128
#define GBK 32
#define SST 40
#define CH_H (GBM * SST)            // 5120 halves per sub-array
#define STG_H (2 * CH_H)            // A, B
#define GEMM_SMEM (2 * STG_H * 2)   // 40960 B

__global__ void __launch_bounds__(256, 3) k_mma_gemm(
        const __half* __restrict__ Ah, const __half* __restrict__ Bh,
        float* __restrict__ Cm, int Nn, const float* __restrict__ bias, int mode,
        const float* __restrict__ sfp) {
    extern __shared__ __half dyn[];
    int tid = threadIdx.x;
    int lane = tid & 31, warp = tid >> 5;
    int wm = warp >> 1, wn = warp & 1;
    int m0 = blockIdx.y * GBM, n0 = blockIdx.x * GBN;
    uint32_t base = smem_u32(dyn);

    float acc[2][8][4];
#pragma unroll
    for (int i = 0; i < 2; i++)
#pragma unroll
        for (int j = 0; j < 8; j++)
#pragma unroll
            for (int r = 0; r < 4; r++) acc[i][j][r] = 0.f;

    uint32_t aoff[2];
#pragma unroll
    for (int mf = 0; mf < 2; mf++)
        aoff[mf] = (uint32_t)(((wm * 32 + mf * 16 + (lane & 15)) * SST + 8 * (lane >> 4)) * 2);
    uint32_t boff[4];
#pragma unroll
    for (int nfp = 0; nfp < 4; nfp++)
        boff[nfp] = (uint32_t)(((wn * 64 + nfp * 16 + (lane & 7) + 8 * (lane >> 4)) * SST
                                + 8 * ((lane >> 3) & 1)) * 2);

    int lrow = tid >> 2;
    int lc = (tid & 3) * 8;

#define GISSUE(ck, st) do { \
    int kb_ = (ck) * GBK; \
    uint32_t sb_ = base + (uint32_t)((st) * STG_H * 2); \
    _Pragma("unroll") \
    for (int half_ = 0; half_ < 2; half_++) { \
        int row_ = lrow + half_ * 64; \
        uint32_t do_ = (uint32_t)((row_ * SST + lc) * 2); \
        CP16(sb_ + do_, gptr(Ah + (size_t)(m0 + row_) * CC + kb_ + lc)); \
        int ok_ = (n0 + row_ < Nn) ? 16 : 0; \
        int br_ = (n0 + row_ < Nn) ? row_ : 0; \
        CP16Z(sb_ + (uint32_t)(CH_H * 2) + do_, gptr(Bh + (size_t)(n0 + br_) * CC + kb_ + lc), ok_); \
    } \
} while (0)

    GISSUE(0, 0);
    CPCOMMIT();

    for (int ck = 0; ck < 17; ck++) {
        if (ck < 16) {
            GISSUE(ck + 1, (ck + 1) & 1);
            CPCOMMIT();
            CPWAIT1();
        } else {
            CPWAIT0();
        }
        __syncthreads();

        uint32_t sb = base + (uint32_t)((ck & 1) * STG_H * 2);
        uint32_t bAh = sb;
        uint32_t bBh = sb + CH_H * 2;
#pragma unroll
        for (int ks = 0; ks < 2; ks++) {
            uint32_t kadd = (uint32_t)(ks * 16 * 2);
            uint32_t ah[2][4];
#pragma unroll
            for (int mf = 0; mf < 2; mf++)
                LDSM4(ah[mf][0], ah[mf][1], ah[mf][2], ah[mf][3], bAh + aoff[mf] + kadd);
#pragma unroll
            for (int nfp = 0; nfp < 4; nfp++) {
                uint32_t bh4[4];
                LDSM4(bh4[0], bh4[1], bh4[2], bh4[3], bBh + boff[nfp] + kadd);
#pragma unroll
                for (int mf = 0; mf < 2; mf++)
#pragma unroll
                    for (int sub = 0; sub < 2; sub++) {
                        int nf = nfp * 2 + sub;
                        MMAH(acc[mf][nf], ah[mf], bh4 + 2 * sub);
                    }
            }
        }
        __syncthreads();
    }
#undef GISSUE

    if (mode == 0) {
#pragma unroll
        for (int mf = 0; mf < 2; mf++) {
            int r0 = m0 + wm * 32 + mf * 16 + (lane >> 2);
#pragma unroll
            for (int nf = 0; nf < 8; nf++) {
                int col = n0 + wn * 64 + nf * 8 + 2 * (lane & 3);
                if (col < Nn) {
                    float b0 = bias ? bias[col] : 0.f;
                    float b1 = bias ? bias[col + 1] : 0.f;
                    *(float2*)(Cm + (size_t)r0 * Nn + col) =
                        make_float2(acc[mf][nf][0] + b0, acc[mf][nf][1] + b1);
                    *(float2*)(Cm + (size_t)(r0 + 8) * Nn + col) =
                        make_float2(acc[mf][nf][2] + b0, acc[mf][nf][3] + b1);
                }
            }
        }
    } else {
        // scatter: Q/K/V single fp16, layout [bh][n][DP]; K scaled by scl*pos_scale[n]
        const float sf = sfp[0];
        const float scl = rsqrtf((float)HD);
        float ps[2][2];
#pragma unroll
        for (int mf = 0; mf < 2; mf++)
#pragma unroll
            for (int rr = 0; rr < 2; rr++) {
                int row = m0 + wm * 32 + mf * 16 + (lane >> 2) + rr * 8;
                int nn = row & 1023;
                float pos = (float)nn * (1.0f / (NN - 1)) - 0.5f;
                ps[mf][rr] = scl * __expf(-sf * pos * pos);
            }
#pragma unroll
        for (int mf = 0; mf < 2; mf++) {
            int r0 = m0 + wm * 32 + mf * 16 + (lane >> 2);
#pragma unroll
            for (int nf = 0; nf < 8; nf++) {
                int col = n0 + wn * 64 + nf * 8 + 2 * (lane & 3);
                if (col < QC) {
                    int s = (col >= 1088) ? 2 : (col >= 544 ? 1 : 0);
                    int rem = col - s * 544;
                    int hh = rem / 68;
                    int d = rem - hh * 68;
                    __half* D = (s == 0) ? g_qh : (s == 1) ? g_kh : g_vh;
#pragma unroll
                    for (int rr = 0; rr < 2; rr++) {
                        int row = r0 + rr * 8;
                        int bb = row >> 10, nn = row & 1023;
                        size_t ad = ((size_t)(bb * HH + hh) * NN + nn) * DP + d;
                        float m = (s == 1) ? ps[mf][rr] : 1.0f;
                        *(uint32_t*)(D + ad) =
                            packh2(acc[mf][nf][rr * 2] * m, acc[mf][nf][rr * 2 + 1] * m);
                    }
                }
            }
        }
    }
}

// ---------------------------------------------------------------------------
// Flash attention: single fp16 operands, fp32 accum. K pre-scaled.
// 2-stage cp.async pipeline. V via ldmatrix.trans. 9 PV output frags (drop pad).
// ---------------------------------------------------------------------------
#define AQT 128
#define AKT 64
#define KSTR 88
#define A_VH (AKT * KSTR)                // 5632
#define ASTG_H (2 * AKT * KSTR)          // 11264 halves
#define ATTN_SMEM (2 * ASTG_H * 2)       // 45056 bytes

__global__ void __launch_bounds__(256) k_attn_mma() {
    extern __shared__ __half adyn[];

    int tid = threadIdx.x, lane = tid & 31, warp = tid >> 5;
    int b = blockIdx.z, h = blockIdx.y, q0 = blockIdx.x * AQT;
    int bh = b * HH + h;
    uint32_t abase = smem_u32(adyn);

    uint32_t aoff = (uint32_t)(((warp * 16 + (lane & 15)) * KSTR + 8 * (lane >> 4)) * 2);
    uint32_t boffS[4];
#pragma unroll
    for (int nfp = 0; nfp < 4; nfp++)
        boffS[nfp] = (uint32_t)(((nfp * 16 + (lane & 7) + 8 * (lane >> 4)) * KSTR
                                 + 8 * ((lane >> 3) & 1)) * 2);
    uint32_t vrow = (uint32_t)((((lane & 15) * KSTR) + (lane >> 4) * 8) * 2);

    // ---- stage Q through smem, extract A-frags ----
    uint32_t qh[5][4];
    {
        const __half* Qg = g_qh + ((size_t)bh * NN + q0) * DP;
        for (int idx = tid; idx < AQT * 10; idx += 256) {
            int r = idx / 10, c = idx - r * 10;
            *(uint4*)(adyn + r * KSTR + c * 8) = *(const uint4*)(Qg + r * DP + c * 8);
        }
        __syncthreads();
#pragma unroll
        for (int kc = 0; kc < 5; kc++)
            LDSM4(qh[kc][0], qh[kc][1], qh[kc][2], qh[kc][3], abase + aoff + kc * 32);
        __syncthreads();     // Q region reused by the K/V pipeline
    }

    float accO[9][4];
#pragma unroll
    for (int i = 0; i < 9; i++)
#pragma unroll
        for (int r = 0; r < 4; r++) accO[i][r] = 0.f;
    float mr0 = -1e30f, mr1 = -1e30f, lr0 = 0.f, lr1 = 0.f;

#define AISSUE(kt_, st) do { \
    uint32_t sb_ = abase + (uint32_t)((st) * ASTG_H * 2); \
    for (int idx = tid; idx < AKT * 10; idx += 256) { \
        int r_ = idx / 10, c_ = idx - r_ * 10; \
        size_t go_ = ((size_t)bh * NN + (kt_) + r_) * DP + c_ * 8; \
        uint32_t do_ = (uint32_t)((r_ * KSTR + c_ * 8) * 2); \
        CP16(sb_ + do_, gptr(g_kh + go_)); \
        CP16(sb_ + (uint32_t)(A_VH * 2) + do_, gptr(g_vh + go_)); \
    } \
} while (0)

    AISSUE(0, 0);
    CPCOMMIT();

    for (int t = 0; t < 16; t++) {
        if (t < 15) {
            AISSUE((t + 1) * AKT, (t + 1) & 1);
            CPCOMMIT();
            CPWAIT1();
        } else {
            CPWAIT0();
        }
        __syncthreads();

        int st = t & 1;
        uint32_t sb = abase + (uint32_t)(st * ASTG_H * 2);
        uint32_t bK0 = sb;
        uint32_t bV0 = sb + A_VH * 2;

        // ---- S = Q K^T (K pre-scaled by scl*pos_scale) ----
        float sacc[8][4];
#pragma unroll
        for (int i = 0; i < 8; i++)
#pragma unroll
            for (int r = 0; r < 4; r++) sacc[i][r] = 0.f;
#pragma unroll
        for (int kc = 0; kc < 5; kc++) {
            uint32_t kadd = kc * 32;
#pragma unroll
            for (int nfp = 0; nfp < 4; nfp++) {
                uint32_t kbh[4];
                LDSM4(kbh[0], kbh[1], kbh[2], kbh[3], bK0 + boffS[nfp] + kadd);
#pragma unroll
                for (int sub = 0; sub < 2; sub++)
                    MMAH(sacc[nfp * 2 + sub], qh[kc], kbh + 2 * sub);
            }
        }

        // ---- online softmax ----
        float tm0 = -1e30f, tm1 = -1e30f;
#pragma unroll
        for (int nf = 0; nf < 8; nf++) {
            tm0 = fmaxf(tm0, fmaxf(sacc[nf][0], sacc[nf][1]));
            tm1 = fmaxf(tm1, fmaxf(sacc[nf][2], sacc[nf][3]));
        }
        tm0 = fmaxf(tm0, __shfl_xor_sync(0xffffffffu, tm0, 1));
        tm0 = fmaxf(tm0, __shfl_xor_sync(0xffffffffu, tm0, 2));
        tm1 = fmaxf(tm1, __shfl_xor_sync(0xffffffffu, tm1, 1));
        tm1 = fmaxf(tm1, __shfl_xor_sync(0xffffffffu, tm1, 2));
        float mn0 = fmaxf(mr0, tm0), mn1 = fmaxf(mr1, tm1);
        float corr0 = __expf(mr0 - mn0), corr1 = __expf(mr1 - mn1);
        float s0 = 0.f, s1 = 0.f;
#pragma unroll
        for (int nf = 0; nf < 8; nf++) {
            sacc[nf][0] = __expf(sacc[nf][0] - mn0);
            sacc[nf][1] = __expf(sacc[nf][1] - mn0);
            sacc[nf][2] = __expf(sacc[nf][2] - mn1);
            sacc[nf][3] = __expf(sacc[nf][3] - mn1);
            s0 += sacc[nf][0] + sacc[nf][1];
            s1 += sacc[nf][2] + sacc[nf][3];
        }
        s0 += __shfl_xor_sync(0xffffffffu, s0, 1);
        s0 += __shfl_xor_sync(0xffffffffu, s0, 2);
        s1 += __shfl_xor_sync(0xffffffffu, s1, 1);
        s1 += __shfl_xor_sync(0xffffffffu, s1, 2);
        lr0 = lr0 * corr0 + s0;
        lr1 = lr1 * corr1 + s1;
        mr0 = mn0; mr1 = mn1;
#pragma unroll
        for (int nf = 0; nf < 9; nf++) {
            accO[nf][0] *= corr0; accO[nf][1] *= corr0;
            accO[nf][2] *= corr1; accO[nf][3] *= corr1;
        }

        // ---- pack P into A-frags (fp16) ----
        uint32_t pA[4][4];
#pragma unroll
        for (int g = 0; g < 4; g++) {
            pA[g][0] = packh2(sacc[2 * g][0], sacc[2 * g][1]);
            pA[g][1] = packh2(sacc[2 * g][2], sacc[2 * g][3]);
            pA[g][2] = packh2(sacc[2 * g + 1][0], sacc[2 * g + 1][1]);
            pA[g][3] = packh2(sacc[2 * g + 1][2], sacc[2 * g + 1][3]);
        }

        // ---- O += P V (trans-ldmatrix V from [keys][DP]); skip all-pad frag ----
#pragma unroll
        for (int kk = 0; kk < 4; kk++) {
            uint32_t kadd = (uint32_t)(kk * 16 * KSTR * 2);
#pragma unroll
            for (int nfp = 0; nfp < 5; nfp++) {
                uint32_t voff = vrow + kadd + (uint32_t)(nfp * 16 * 2);
                uint32_t vbh[4];
                LDSM4T(vbh[0], vbh[1], vbh[2], vbh[3], bV0 + voff);
                MMAH(accO[nfp * 2], pA[kk], vbh);
                if (nfp < 4) MMAH(accO[nfp * 2 + 1], pA[kk], vbh + 2);
            }
        }
        __syncthreads();
    }
#undef AISSUE

    // ---- epilogue: normalize, store fp16 into proj-A buffer ----
    float inv0 = 1.0f / lr0, inv1 = 1.0f / lr1;
    int r = lane >> 2;
    int n_0 = q0 + warp * 16 + r;
#pragma unroll
    for (int nf = 0; nf < 9; nf++) {
        int d0 = nf * 8 + 2 * (lane & 3);
        if (d0 + 1 < HD) {
            size_t a0 = ((size_t)(b * NN + n_0)) * CC + h * HD + d0;
            size_t a1 = ((size_t)(b * NN + n_0 + 8)) * CC + h * HD + d0;
            *(uint32_t*)(g_ah + a0) = packh2(accO[nf][0] * inv0, accO[nf][1] * inv0);
            *(uint32_t*)(g_ah + a1) = packh2(accO[nf][2] * inv1, accO[nf][3] * inv1);
        }
    }
}

// ---------------------------------------------------------------------------
extern "C" void kernel_launch(void* const* d_in, const int* in_sizes, int n_in,
                              void* d_out, int out_size) {
    const float* x       = (const float*)d_in[0];
    const float* norm_g  = (const float*)d_in[1];
    const float* norm_b  = (const float*)d_in[2];
    const float* ap_w    = (const float*)d_in[3];
    const float* ap_b    = (const float*)d_in[4];
    const float* norm2_g = (const float*)d_in[5];
    const float* norm2_b = (const float*)d_in[6];
    const float* qkv_w   = (const float*)d_in[7];
    const float* proj_w  = (const float*)d_in[8];
    const float* proj_b  = (const float*)d_in[9];
    const float* scaling = (const float*)d_in[10];
    float* out = (float*)d_out;

    static int attr_set = 0;
    if (!attr_set) {
        cudaFuncSetAttribute(k_mma_gemm, cudaFuncAttributeMaxDynamicSharedMemorySize, GEMM_SMEM);
        cudaFuncSetAttribute(k_attn_mma, cudaFuncAttributeMaxDynamicSharedMemorySize, ATTN_SMEM);
        attr_set = 1;
    }

    __half *p_qb, *p_pb, *p_ah;
    cudaGetSymbolAddress((void**)&p_qb, g_qb);
    cudaGetSymbolAddress((void**)&p_pb, g_pb);
    cudaGetSymbolAddress((void**)&p_ah, g_ah);

    // launch #1: fused preprocessing
    k_pre<<<PRE_PAD, CC>>>(x, norm_g, norm_b, ap_w, ap_b, qkv_w, proj_w);
    // launch #2
    k_softmax_seq<<<Bb * JJ, 256>>>();
    // launch #3
    k_pool_ln<<<Bb * NN, CC>>>(x, norm_g, norm_b, norm2_g, norm2_b);
    // launch #4 (profiled): QKV GEMM (scatters Q/K/V; K pre-scaled)
    k_mma_gemm<<<dim3(13, (Bb * NN) / GBM), 256, GEMM_SMEM>>>(
        p_ah, p_qb, nullptr, QC, nullptr, 1, scaling);
    // launch #5: attention
    k_attn_mma<<<dim3(NN / AQT, HH, Bb), 256, ATTN_SMEM>>>();
    // launch #6: proj GEMM
    k_mma_gemm<<<dim3(5, (Bb * NN) / GBM), 256, GEMM_SMEM>>>(
        p_ah, p_pb, out, CC, proj_b, 0, nullptr);
}

// round 13
// speedup vs baseline: 1.2136x; 1.2136x over previous
#include <cuda_runtime.h>
#include <cuda_fp16.h>
#include <math.h>
#include <stdint.h>

typedef unsigned long long ull;

#define Bb 8
#define NN 1024
#define CC 544
#define JJ 17
#define FF 32
#define HH 8
#define HD 68
#define QC 1632
#define DP 80     // padded head dim

// tensor-core warp ops (family-common PTX, OK on plain sm_103 target)
#define LDSM4(r0,r1,r2,r3,addr) \
    asm volatile("ldmatrix.sync.aligned.m8n8.x4.shared.b16 {%0,%1,%2,%3}, [%4];" \
        : "=r"(r0),"=r"(r1),"=r"(r2),"=r"(r3) : "r"(addr))
#define LDSM4T(r0,r1,r2,r3,addr) \
    asm volatile("ldmatrix.sync.aligned.m8n8.x4.trans.shared.b16 {%0,%1,%2,%3}, [%4];" \
        : "=r"(r0),"=r"(r1),"=r"(r2),"=r"(r3) : "r"(addr))
#define MMAH(d,a,b) \
    asm volatile("mma.sync.aligned.m16n8k16.row.col.f32.f16.f16.f32 " \
        "{%0,%1,%2,%3}, {%4,%5,%6,%7}, {%8,%9}, {%0,%1,%2,%3};" \
        : "+f"((d)[0]),"+f"((d)[1]),"+f"((d)[2]),"+f"((d)[3]) \
        : "r"((a)[0]),"r"((a)[1]),"r"((a)[2]),"r"((a)[3]), "r"((b)[0]),"r"((b)[1]))

#define CP16(dst, src) \
    asm volatile("cp.async.cg.shared.global [%0], [%1], 16;" \
        :: "r"(dst), "l"(src) : "memory")
#define CP16Z(dst, src, sz) \
    asm volatile("cp.async.cg.shared.global [%0], [%1], 16, %2;" \
        :: "r"(dst), "l"(src), "r"(sz) : "memory")
#define CPCOMMIT() asm volatile("cp.async.commit_group;" ::: "memory")
#define CPWAIT1()  asm volatile("cp.async.wait_group 1;" ::: "memory")
#define CPWAIT0()  asm volatile("cp.async.wait_group 0;" ::: "memory")

__device__ __forceinline__ uint32_t smem_u32(const void* p) {
    uint32_t a;
    asm("{ .reg .u64 t; cvta.to.shared.u64 t, %1; cvt.u32.u64 %0, t; }" : "=r"(a) : "l"(p));
    return a;
}
__device__ __forceinline__ const void* gptr(const void* p) {
    return (const void*)__cvta_generic_to_global(p);
}
__device__ __forceinline__ uint32_t packh2(float v0, float v1) {
    __half2 h = __floats2half2_rn(v0, v1);
    return *(uint32_t*)&h;
}

// -------- scratch --------
__device__ float g_sc [(size_t)Bb * NN * JJ];
__device__ float g_w  [(size_t)Bb * NN * JJ];
__device__ __half g_ah [(size_t)Bb * NN * CC];   // GEMM A (xp, then attn-out), fp16
__device__ __half g_qb [(size_t)QC * CC];        // qkv weights fp16
__device__ __half g_pb [(size_t)CC * CC];        // proj weights fp16
__device__ __half g_qh [(size_t)Bb * HH * NN * DP];
__device__ __half g_kh [(size_t)Bb * HH * NN * DP];   // pre-scaled by scl*pos_scale
__device__ __half g_vh [(size_t)Bb * HH * NN * DP];

__device__ __forceinline__ float wsum(float v) {
#pragma unroll
    for (int o = 16; o > 0; o >>= 1) v += __shfl_xor_sync(0xffffffffu, v, o);
    return v;
}
__device__ __forceinline__ float wmax(float v) {
#pragma unroll
    for (int o = 16; o > 0; o >>= 1) v = fmaxf(v, __shfl_xor_sync(0xffffffffu, v, o));
    return v;
}

// ---------------------------------------------------------------------------
// Kernel 1 (fused preprocessing): scores + weight fp16 converts + pad zeroing
// ---------------------------------------------------------------------------
#define PRE_SCORE 8192
#define PRE_CVTQ  (PRE_SCORE + 408)
#define PRE_CVTP  (PRE_CVTQ + 136)
#define PRE_PAD   (PRE_CVTP + 1446)

__global__ void k_pre(const float* __restrict__ x,
                      const float* __restrict__ ng,
                      const float* __restrict__ nb,
                      const float* __restrict__ apw,
                      const float* __restrict__ apb,
                      const float* __restrict__ qkv_w,
                      const float* __restrict__ proj_w) {
    int blk = blockIdx.x;
    int tid = threadIdx.x;
    if (blk < PRE_SCORE) {
        int bn = blk;
        int j = tid >> 5, f = tid & 31;
        float v = x[(size_t)bn * CC + j * FF + f];
        float mu = wsum(v) * (1.0f / FF);
        float d = v - mu;
        float var = wsum(d * d) * (1.0f / FF);
        float xn = d * rsqrtf(var + 1e-5f) * ng[f] + nb[f];
        float sc = wsum(xn * apw[f]);
        if (f == 0) g_sc[(size_t)bn * JJ + j] = sc + apb[0];
    } else if (blk < PRE_CVTQ) {
        int idx = (blk - PRE_SCORE) * 544 + tid;    // < 221952 exactly
        float4 v = ((const float4*)qkv_w)[idx];
        ((uint2*)g_qb)[idx] = make_uint2(packh2(v.x, v.y), packh2(v.z, v.w));
    } else if (blk < PRE_CVTP) {
        int idx = (blk - PRE_CVTQ) * 544 + tid;     // < 73984 exactly
        float4 v = ((const float4*)proj_w)[idx];
        ((uint2*)g_pb)[idx] = make_uint2(packh2(v.x, v.y), packh2(v.z, v.w));
    } else {
        int idx = (blk - PRE_CVTP) * 544 + tid;
        if (idx < 64 * 1024 * (DP - HD)) {
            int bhn = idx / (DP - HD), d = HD + (idx - bhn * (DP - HD));
            size_t ad = (size_t)bhn * DP + d;
            __half z = __float2half(0.f);
            g_qh[ad] = z; g_kh[ad] = z;
        }
    }
}

// ---------------------------------------------------------------------------
// Kernel 2: softmax over sequence axis N per (b, joint)
// ---------------------------------------------------------------------------
__global__ void k_softmax_seq() {
    int bj = blockIdx.x;
    int b = bj / JJ, j = bj - b * JJ;
    int tid = threadIdx.x;
    const float* base = g_sc + (size_t)b * NN * JJ + j;

    float v[4];
#pragma unroll
    for (int i = 0; i < 4; i++) v[i] = base[(size_t)(tid + i * 256) * JJ];

    __shared__ float red[8];
    __shared__ float bc;
    int wid = tid >> 5, lane = tid & 31;

    float mx = fmaxf(fmaxf(v[0], v[1]), fmaxf(v[2], v[3]));
    mx = wmax(mx);
    if (lane == 0) red[wid] = mx;
    __syncthreads();
    if (tid == 0) {
        float m = red[0];
        for (int i = 1; i < 8; i++) m = fmaxf(m, red[i]);
        bc = m;
    }
    __syncthreads();
    mx = bc;
    __syncthreads();

    float se = 0.f;
#pragma unroll
    for (int i = 0; i < 4; i++) { v[i] = __expf(v[i] - mx); se += v[i]; }
    se = wsum(se);
    if (lane == 0) red[wid] = se;
    __syncthreads();
    if (tid == 0) {
        float s = 0.f;
        for (int i = 0; i < 8; i++) s += red[i];
        bc = 1.0f / s;
    }
    __syncthreads();
    float inv = bc;

    float* wbase = g_w + (size_t)b * NN * JJ + j;
#pragma unroll
    for (int i = 0; i < 4; i++) wbase[(size_t)(tid + i * 256) * JJ] = v[i] * inv;
}

// ---------------------------------------------------------------------------
// Kernel 3: recompute joint-LN from x, pool, LN over C -> fp16
// ---------------------------------------------------------------------------
__global__ void k_pool_ln(const float* __restrict__ x,
                          const float* __restrict__ ng,
                          const float* __restrict__ nb,
                          const float* __restrict__ g2,
                          const float* __restrict__ b2) {
    int bn = blockIdx.x;
    int c = threadIdx.x;
    int wid = c >> 5, lane = c & 31;
    __shared__ float red[17];
    __shared__ float bc0, bc1;

    float xv = x[(size_t)bn * CC + c];
    float mu_j = wsum(xv) * (1.0f / FF);
    float dj = xv - mu_j;
    float var_j = wsum(dj * dj) * (1.0f / FF);
    float xn = dj * rsqrtf(var_j + 1e-5f) * ng[lane] + nb[lane];

    float v = xn * g_w[(size_t)bn * JJ + wid];

    float s = wsum(v);
    if (lane == 0) red[wid] = s;
    __syncthreads();
    if (wid == 0) {
        float t = (lane < 17) ? red[lane] : 0.f;
        t = wsum(t);
        if (lane == 0) bc0 = t * (1.0f / CC);
    }
    __syncthreads();
    float mu = bc0;
    float d = v - mu;

    float s2 = wsum(d * d);
    if (lane == 0) red[wid] = s2;
    __syncthreads();
    if (wid == 0) {
        float t = (lane < 17) ? red[lane] : 0.f;
        t = wsum(t);
        if (lane == 0) bc1 = t * (1.0f / CC);
    }
    __syncthreads();
    float var = bc1;

    float xp = d * rsqrtf(var + 1e-5f) * g2[c] + b2[c];
    g_ah[(size_t)bn * CC + c] = __float2half_rn(xp);
}

// ---------------------------------------------------------------------------
// cp.async double-buffered mma.sync fp16 GEMM.
// mode 0: fp32 C (+bias). mode 1: scatter QKV (K pre-scaled by scl*pos_scale).
// ---------------------------------------------------------------------------
#define GBM 128
#define GBN 128
#define GBK 32
#define SST 40
#define CH_H (GBM * SST)            // 5120 halves per sub-array
#define STG_H (2 * CH_H)            // A, B
#define GEMM_SMEM (2 * STG_H * 2)   // 40960 B

__global__ void __launch_bounds__(256) k_mma_gemm(
        const __half* __restrict__ Ah, const __half* __restrict__ Bh,
        float* __restrict__ Cm, int Nn, const float* __restrict__ bias, int mode,
        const float* __restrict__ sfp) {
    extern __shared__ __half dyn[];
    int tid = threadIdx.x;
    int lane = tid & 31, warp = tid >> 5;
    int wm = warp >> 1, wn = warp & 1;
    int m0 = blockIdx.y * GBM, n0 = blockIdx.x * GBN;
    uint32_t base = smem_u32(dyn);

    float acc[2][8][4];
#pragma unroll
    for (int i = 0; i < 2; i++)
#pragma unroll
        for (int j = 0; j < 8; j++)
#pragma unroll
            for (int r = 0; r < 4; r++) acc[i][j][r] = 0.f;

    uint32_t aoff[2];
#pragma unroll
    for (int mf = 0; mf < 2; mf++)
        aoff[mf] = (uint32_t)(((wm * 32 + mf * 16 + (lane & 15)) * SST + 8 * (lane >> 4)) * 2);
    uint32_t boff[4];
#pragma unroll
    for (int nfp = 0; nfp < 4; nfp++)
        boff[nfp] = (uint32_t)(((wn * 64 + nfp * 16 + (lane & 7) + 8 * (lane >> 4)) * SST
                                + 8 * ((lane >> 3) & 1)) * 2);

    int lrow = tid >> 2;
    int lc = (tid & 3) * 8;

#define GISSUE(ck, st) do { \
    int kb_ = (ck) * GBK; \
    uint32_t sb_ = base + (uint32_t)((st) * STG_H * 2); \
    _Pragma("unroll") \
    for (int half_ = 0; half_ < 2; half_++) { \
        int row_ = lrow + half_ * 64; \
        uint32_t do_ = (uint32_t)((row_ * SST + lc) * 2); \
        CP16(sb_ + do_, gptr(Ah + (size_t)(m0 + row_) * CC + kb_ + lc)); \
        int ok_ = (n0 + row_ < Nn) ? 16 : 0; \
        int br_ = (n0 + row_ < Nn) ? row_ : 0; \
        CP16Z(sb_ + (uint32_t)(CH_H * 2) + do_, gptr(Bh + (size_t)(n0 + br_) * CC + kb_ + lc), ok_); \
    } \
} while (0)

    GISSUE(0, 0);
    CPCOMMIT();

    for (int ck = 0; ck < 17; ck++) {
        if (ck < 16) {
            GISSUE(ck + 1, (ck + 1) & 1);
            CPCOMMIT();
            CPWAIT1();
        } else {
            CPWAIT0();
        }
        __syncthreads();

        uint32_t sb = base + (uint32_t)((ck & 1) * STG_H * 2);
        uint32_t bAh = sb;
        uint32_t bBh = sb + CH_H * 2;
#pragma unroll
        for (int ks = 0; ks < 2; ks++) {
            uint32_t kadd = (uint32_t)(ks * 16 * 2);
            uint32_t ah[2][4];
#pragma unroll
            for (int mf = 0; mf < 2; mf++)
                LDSM4(ah[mf][0], ah[mf][1], ah[mf][2], ah[mf][3], bAh + aoff[mf] + kadd);
#pragma unroll
            for (int nfp = 0; nfp < 4; nfp++) {
                uint32_t bh4[4];
                LDSM4(bh4[0], bh4[1], bh4[2], bh4[3], bBh + boff[nfp] + kadd);
#pragma unroll
                for (int mf = 0; mf < 2; mf++)
#pragma unroll
                    for (int sub = 0; sub < 2; sub++) {
                        int nf = nfp * 2 + sub;
                        MMAH(acc[mf][nf], ah[mf], bh4 + 2 * sub);
                    }
            }
        }
        __syncthreads();
    }
#undef GISSUE

    if (mode == 0) {
#pragma unroll
        for (int mf = 0; mf < 2; mf++) {
            int r0 = m0 + wm * 32 + mf * 16 + (lane >> 2);
#pragma unroll
            for (int nf = 0; nf < 8; nf++) {
                int col = n0 + wn * 64 + nf * 8 + 2 * (lane & 3);
                if (col < Nn) {
                    float b0 = bias ? bias[col] : 0.f;
                    float b1 = bias ? bias[col + 1] : 0.f;
                    *(float2*)(Cm + (size_t)r0 * Nn + col) =
                        make_float2(acc[mf][nf][0] + b0, acc[mf][nf][1] + b1);
                    *(float2*)(Cm + (size_t)(r0 + 8) * Nn + col) =
                        make_float2(acc[mf][nf][2] + b0, acc[mf][nf][3] + b1);
                }
            }
        }
    } else {
        // scatter: Q/K/V single fp16, layout [bh][n][DP]; K scaled by scl*pos_scale[n]
        const float sf = sfp[0];
        const float scl = rsqrtf((float)HD);
        float ps[2][2];
#pragma unroll
        for (int mf = 0; mf < 2; mf++)
#pragma unroll
            for (int rr = 0; rr < 2; rr++) {
                int row = m0 + wm * 32 + mf * 16 + (lane >> 2) + rr * 8;
                int nn = row & 1023;
                float pos = (float)nn * (1.0f / (NN - 1)) - 0.5f;
                ps[mf][rr] = scl * __expf(-sf * pos * pos);
            }
#pragma unroll
        for (int mf = 0; mf < 2; mf++) {
            int r0 = m0 + wm * 32 + mf * 16 + (lane >> 2);
#pragma unroll
            for (int nf = 0; nf < 8; nf++) {
                int col = n0 + wn * 64 + nf * 8 + 2 * (lane & 3);
                if (col < QC) {
                    int s = (col >= 1088) ? 2 : (col >= 544 ? 1 : 0);
                    int rem = col - s * 544;
                    int hh = rem / 68;
                    int d = rem - hh * 68;
                    __half* D = (s == 0) ? g_qh : (s == 1) ? g_kh : g_vh;
#pragma unroll
                    for (int rr = 0; rr < 2; rr++) {
                        int row = r0 + rr * 8;
                        int bb = row >> 10, nn = row & 1023;
                        size_t ad = ((size_t)(bb * HH + hh) * NN + nn) * DP + d;
                        float m = (s == 1) ? ps[mf][rr] : 1.0f;
                        *(uint32_t*)(D + ad) =
                            packh2(acc[mf][nf][rr * 2] * m, acc[mf][nf][rr * 2 + 1] * m);
                    }
                }
            }
        }
    }
}

// ---------------------------------------------------------------------------
// Flash attention: single fp16 operands, fp32 accum. K pre-scaled.
// 2-stage cp.async pipeline. V via ldmatrix.trans. 9 PV output frags (drop pad).
// ---------------------------------------------------------------------------
#define AQT 128
#define AKT 64
#define KSTR 88
#define A_VH (AKT * KSTR)                // 5632
#define ASTG_H (2 * AKT * KSTR)          // 11264 halves
#define ATTN_SMEM (2 * ASTG_H * 2)       // 45056 bytes

__global__ void __launch_bounds__(256) k_attn_mma() {
    extern __shared__ __half adyn[];

    int tid = threadIdx.x, lane = tid & 31, warp = tid >> 5;
    int b = blockIdx.z, h = blockIdx.y, q0 = blockIdx.x * AQT;
    int bh = b * HH + h;
    uint32_t abase = smem_u32(adyn);

    uint32_t aoff = (uint32_t)(((warp * 16 + (lane & 15)) * KSTR + 8 * (lane >> 4)) * 2);
    uint32_t boffS[4];
#pragma unroll
    for (int nfp = 0; nfp < 4; nfp++)
        boffS[nfp] = (uint32_t)(((nfp * 16 + (lane & 7) + 8 * (lane >> 4)) * KSTR
                                 + 8 * ((lane >> 3) & 1)) * 2);
    uint32_t vrow = (uint32_t)((((lane & 15) * KSTR) + (lane >> 4) * 8) * 2);

    // ---- stage Q through smem, extract A-frags ----
    uint32_t qh[5][4];
    {
        const __half* Qg = g_qh + ((size_t)bh * NN + q0) * DP;
        for (int idx = tid; idx < AQT * 10; idx += 256) {
            int r = idx / 10, c = idx - r * 10;
            *(uint4*)(adyn + r * KSTR + c * 8) = *(const uint4*)(Qg + r * DP + c * 8);
        }
        __syncthreads();
#pragma unroll
        for (int kc = 0; kc < 5; kc++)
            LDSM4(qh[kc][0], qh[kc][1], qh[kc][2], qh[kc][3], abase + aoff + kc * 32);
        __syncthreads();     // Q region reused by the K/V pipeline
    }

    float accO[9][4];
#pragma unroll
    for (int i = 0; i < 9; i++)
#pragma unroll
        for (int r = 0; r < 4; r++) accO[i][r] = 0.f;
    float mr0 = -1e30f, mr1 = -1e30f, lr0 = 0.f, lr1 = 0.f;

#define AISSUE(kt_, st) do { \
    uint32_t sb_ = abase + (uint32_t)((st) * ASTG_H * 2); \
    for (int idx = tid; idx < AKT * 10; idx += 256) { \
        int r_ = idx / 10, c_ = idx - r_ * 10; \
        size_t go_ = ((size_t)bh * NN + (kt_) + r_) * DP + c_ * 8; \
        uint32_t do_ = (uint32_t)((r_ * KSTR + c_ * 8) * 2); \
        CP16(sb_ + do_, gptr(g_kh + go_)); \
        CP16(sb_ + (uint32_t)(A_VH * 2) + do_, gptr(g_vh + go_)); \
    } \
} while (0)

    AISSUE(0, 0);
    CPCOMMIT();

    for (int t = 0; t < 16; t++) {
        if (t < 15) {
            AISSUE((t + 1) * AKT, (t + 1) & 1);
            CPCOMMIT();
            CPWAIT1();
        } else {
            CPWAIT0();
        }
        __syncthreads();

        int st = t & 1;
        uint32_t sb = abase + (uint32_t)(st * ASTG_H * 2);
        uint32_t bK0 = sb;
        uint32_t bV0 = sb + A_VH * 2;

        // ---- S = Q K^T (K pre-scaled by scl*pos_scale) ----
        float sacc[8][4];
#pragma unroll
        for (int i = 0; i < 8; i++)
#pragma unroll
            for (int r = 0; r < 4; r++) sacc[i][r] = 0.f;
#pragma unroll
        for (int kc = 0; kc < 5; kc++) {
            uint32_t kadd = kc * 32;
#pragma unroll
            for (int nfp = 0; nfp < 4; nfp++) {
                uint32_t kbh[4];
                LDSM4(kbh[0], kbh[1], kbh[2], kbh[3], bK0 + boffS[nfp] + kadd);
#pragma unroll
                for (int sub = 0; sub < 2; sub++)
                    MMAH(sacc[nfp * 2 + sub], qh[kc], kbh + 2 * sub);
            }
        }

        // ---- online softmax ----
        float tm0 = -1e30f, tm1 = -1e30f;
#pragma unroll
        for (int nf = 0; nf < 8; nf++) {
            tm0 = fmaxf(tm0, fmaxf(sacc[nf][0], sacc[nf][1]));
            tm1 = fmaxf(tm1, fmaxf(sacc[nf][2], sacc[nf][3]));
        }
        tm0 = fmaxf(tm0, __shfl_xor_sync(0xffffffffu, tm0, 1));
        tm0 = fmaxf(tm0, __shfl_xor_sync(0xffffffffu, tm0, 2));
        tm1 = fmaxf(tm1, __shfl_xor_sync(0xffffffffu, tm1, 1));
        tm1 = fmaxf(tm1, __shfl_xor_sync(0xffffffffu, tm1, 2));
        float mn0 = fmaxf(mr0, tm0), mn1 = fmaxf(mr1, tm1);
        float corr0 = __expf(mr0 - mn0), corr1 = __expf(mr1 - mn1);
        float s0 = 0.f, s1 = 0.f;
#pragma unroll
        for (int nf = 0; nf < 8; nf++) {
            sacc[nf][0] = __expf(sacc[nf][0] - mn0);
            sacc[nf][1] = __expf(sacc[nf][1] - mn0);
            sacc[nf][2] = __expf(sacc[nf][2] - mn1);
            sacc[nf][3] = __expf(sacc[nf][3] - mn1);
            s0 += sacc[nf][0] + sacc[nf][1];
            s1 += sacc[nf][2] + sacc[nf][3];
        }
        s0 += __shfl_xor_sync(0xffffffffu, s0, 1);
        s0 += __shfl_xor_sync(0xffffffffu, s0, 2);
        s1 += __shfl_xor_sync(0xffffffffu, s1, 1);
        s1 += __shfl_xor_sync(0xffffffffu, s1, 2);
        lr0 = lr0 * corr0 + s0;
        lr1 = lr1 * corr1 + s1;
        mr0 = mn0; mr1 = mn1;
#pragma unroll
        for (int nf = 0; nf < 9; nf++) {
            accO[nf][0] *= corr0; accO[nf][1] *= corr0;
            accO[nf][2] *= corr1; accO[nf][3] *= corr1;
        }

        // ---- pack P into A-frags (fp16) ----
        uint32_t pA[4][4];
#pragma unroll
        for (int g = 0; g < 4; g++) {
            pA[g][0] = packh2(sacc[2 * g][0], sacc[2 * g][1]);
            pA[g][1] = packh2(sacc[2 * g][2], sacc[2 * g][3]);
            pA[g][2] = packh2(sacc[2 * g + 1][0], sacc[2 * g + 1][1]);
            pA[g][3] = packh2(sacc[2 * g + 1][2], sacc[2 * g + 1][3]);
        }

        // ---- O += P V (trans-ldmatrix V from [keys][DP]); skip all-pad frag ----
#pragma unroll
        for (int kk = 0; kk < 4; kk++) {
            uint32_t kadd = (uint32_t)(kk * 16 * KSTR * 2);
#pragma unroll
            for (int nfp = 0; nfp < 5; nfp++) {
                uint32_t voff = vrow + kadd + (uint32_t)(nfp * 16 * 2);
                uint32_t vbh[4];
                LDSM4T(vbh[0], vbh[1], vbh[2], vbh[3], bV0 + voff);
                MMAH(accO[nfp * 2], pA[kk], vbh);
                if (nfp < 4) MMAH(accO[nfp * 2 + 1], pA[kk], vbh + 2);
            }
        }
        __syncthreads();
    }
#undef AISSUE

    // ---- epilogue: normalize, store fp16 into proj-A buffer ----
    float inv0 = 1.0f / lr0, inv1 = 1.0f / lr1;
    int r = lane >> 2;
    int n_0 = q0 + warp * 16 + r;
#pragma unroll
    for (int nf = 0; nf < 9; nf++) {
        int d0 = nf * 8 + 2 * (lane & 3);
        if (d0 + 1 < HD) {
            size_t a0 = ((size_t)(b * NN + n_0)) * CC + h * HD + d0;
            size_t a1 = ((size_t)(b * NN + n_0 + 8)) * CC + h * HD + d0;
            *(uint32_t*)(g_ah + a0) = packh2(accO[nf][0] * inv0, accO[nf][1] * inv0);
            *(uint32_t*)(g_ah + a1) = packh2(accO[nf][2] * inv1, accO[nf][3] * inv1);
        }
    }
}

// ---------------------------------------------------------------------------
extern "C" void kernel_launch(void* const* d_in, const int* in_sizes, int n_in,
                              void* d_out, int out_size) {
    const float* x       = (const float*)d_in[0];
    const float* norm_g  = (const float*)d_in[1];
    const float* norm_b  = (const float*)d_in[2];
    const float* ap_w    = (const float*)d_in[3];
    const float* ap_b    = (const float*)d_in[4];
    const float* norm2_g = (const float*)d_in[5];
    const float* norm2_b = (const float*)d_in[6];
    const float* qkv_w   = (const float*)d_in[7];
    const float* proj_w  = (const float*)d_in[8];
    const float* proj_b  = (const float*)d_in[9];
    const float* scaling = (const float*)d_in[10];
    float* out = (float*)d_out;

    static int attr_set = 0;
    if (!attr_set) {
        cudaFuncSetAttribute(k_mma_gemm, cudaFuncAttributeMaxDynamicSharedMemorySize, GEMM_SMEM);
        cudaFuncSetAttribute(k_attn_mma, cudaFuncAttributeMaxDynamicSharedMemorySize, ATTN_SMEM);
        attr_set = 1;
    }

    __half *p_qb, *p_pb, *p_ah;
    cudaGetSymbolAddress((void**)&p_qb, g_qb);
    cudaGetSymbolAddress((void**)&p_pb, g_pb);
    cudaGetSymbolAddress((void**)&p_ah, g_ah);

    // launch #1: fused preprocessing
    k_pre<<<PRE_PAD, CC>>>(x, norm_g, norm_b, ap_w, ap_b, qkv_w, proj_w);
    // launch #2
    k_softmax_seq<<<Bb * JJ, 256>>>();
    // launch #3
    k_pool_ln<<<Bb * NN, CC>>>(x, norm_g, norm_b, norm2_g, norm2_b);
    // launch #4 (profiled): QKV GEMM (scatters Q/K/V; K pre-scaled)
    k_mma_gemm<<<dim3(13, (Bb * NN) / GBM), 256, GEMM_SMEM>>>(
        p_ah, p_qb, nullptr, QC, nullptr, 1, scaling);
    // launch #5: attention
    k_attn_mma<<<dim3(NN / AQT, HH, Bb), 256, ATTN_SMEM>>>();
    // launch #6: proj GEMM
    k_mma_gemm<<<dim3(5, (Bb * NN) / GBM), 256, GEMM_SMEM>>>(
        p_ah, p_pb, out, CC, proj_b, 0, nullptr);
}